// round 13
// baseline (speedup 1.0000x reference)
#include <cuda_runtime.h>

#define NV   4096
#define NSV  256
#define BB   2
#define GXD  128
#define GYD  128
#define GZD  16
#define CC   128
#define NCL  20
#define NH   8
#define DHD  16
#define MAPSZ (BB*GXD*GYD*GZD)
#define EPSF 1e-5f
#define GQ   8

// ---------------- packed f32x2 helpers ----------------
typedef unsigned long long ull;
__device__ __forceinline__ ull pk(float lo, float hi) {
    ull r; asm("mov.b64 %0, {%1,%2};" : "=l"(r) : "f"(lo), "f"(hi)); return r;
}
__device__ __forceinline__ ull pk2(float2 f) { return pk(f.x, f.y); }
__device__ __forceinline__ void upk(float& lo, float& hi, ull v) {
    asm("mov.b64 {%0,%1}, %2;" : "=f"(lo), "=f"(hi) : "l"(v));
}
#define FMA2(d,a,b,c) asm("fma.rn.f32x2 %0, %1, %2, %3;" : "=l"(d) : "l"(a), "l"(b), "l"(c))

// ---------------- device scratch ----------------
struct Acc { float s1[CC]; float s2[CC]; };
__device__ Acc  g_acc;
__device__ int4 g_unq[NSV];
__device__ int  g_members[NSV*16];
__device__ float g_hid[NSV*CC];
__device__ float g_kT[CC*NSV];     // K transposed [c][s]
__device__ float g_v[NSV*CC];      // V natural    [s][c]
__device__ float g_y[NV*CC];
__device__ int   g_map[MAPSZ];     // zero-init; stores n+1 (idempotent per input)
__device__ float g_pweff[4*64];

// ================= k_prep: zero acc, keys, unique, members, pbias fold ====
__global__ void k_prep(const int* __restrict__ idx,
                       const float* __restrict__ pw1, const float* __restrict__ pb1,
                       const float* __restrict__ pg1, const float* __restrict__ pbe1) {
    __shared__ unsigned sflags[256];
    __shared__ unsigned short skeys[NV];
    __shared__ int sscan[256], srank[256], scnt[256];
    __shared__ double dS[18];              // Si[0..9), Su[9..18)
    __shared__ double md[3], Cv[3][3];
    int t = threadIdx.x, lane = t & 31;

    if (t < 128) g_acc.s1[t] = 0.f; else g_acc.s2[t & 127] = 0.f;
    if (t < 18) dS[t] = 0.0;

    sflags[t] = 0u;
    scnt[t] = 0;
    __syncthreads();

    long long m[9] = {0,0,0,0,0,0,0,0,0};
    for (int i = t; i < NV; i += 256) {
        int4 p = ((const int4*)idx)[i];
        int key = ((p.x * 32 + (p.y >> 2)) * 32 + (p.z >> 2)) * 4 + (p.w >> 2);
        skeys[i] = (unsigned short)key;
        atomicOr(&sflags[key >> 5], 1u << (key & 31));
        g_map[((p.x * GXD + p.y) * GYD + p.z) * GZD + p.w] = i + 1;
        long long xs = p.y, ys = p.z, zs = p.w;
        m[0]+=xs; m[1]+=ys; m[2]+=zs; m[3]+=xs*xs; m[4]+=ys*ys; m[5]+=zs*zs;
        m[6]+=xs*ys; m[7]+=xs*zs; m[8]+=ys*zs;
    }
    __syncthreads();

    unsigned w = sflags[t];
    int cnt = __popc(w);
    sscan[t] = cnt; __syncthreads();
    for (int off = 1; off < 256; off <<= 1) {
        int v = (t >= off) ? sscan[t - off] : 0;
        __syncthreads(); sscan[t] += v; __syncthreads();
    }
    int excl = sscan[t] - cnt;
    srank[t] = excl;
    unsigned wb = w;
    while (wb) {
        int bit = __ffs(wb) - 1; wb &= wb - 1;
        int rank = excl + __popc(w & ((1u << bit) - 1u));
        int key = t * 32 + bit;
        int4 u;
        u.w = key & 3; u.z = (key >> 2) & 31; u.y = (key >> 7) & 31; u.x = key >> 12;
        g_unq[rank] = u;
    }
    __syncthreads();

    // members + both moment reductions (atomic into shared doubles; exact: integers)
    for (int i = t; i < NV; i += 256) {
        int key = skeys[i];
        int s = srank[key >> 5] + __popc(sflags[key >> 5] & ((1u << (key & 31)) - 1u));
        int slot = atomicAdd(&scnt[s], 1);
        g_members[s*16 + slot] = i;
    }
    #pragma unroll
    for (int k = 0; k < 9; k++) {
        long long v = m[k];
        for (int o = 16; o; o >>= 1) v += __shfl_xor_sync(~0u, v, o);
        if (lane == 0) atomicAdd(&dS[k], (double)v);
    }
    {
        int4 u = g_unq[t];
        long long xs = u.y, ys = u.z, zs = u.w;
        long long mu9[9] = { xs, ys, zs, xs*xs, ys*ys, zs*zs, xs*ys, xs*zs, ys*zs };
        #pragma unroll
        for (int k = 0; k < 9; k++) {
            long long v = mu9[k];
            for (int o = 16; o; o >>= 1) v += __shfl_xor_sync(~0u, v, o);
            if (lane == 0) atomicAdd(&dS[9 + k], (double)v);
        }
    }
    __syncthreads();

    if (t == 0) {
        double mi[3], mu_[3];
        for (int a = 0; a < 3; a++) {
            mi[a]  = dS[a]     / (double)NV;
            mu_[a] = dS[9 + a] / (double)NSV;
            md[a]  = mi[a] - mu_[a];
        }
        const int pid[3][3] = { {3,6,7}, {6,4,8}, {7,8,5} };
        for (int a = 0; a < 3; a++)
            for (int b = 0; b < 3; b++)
                Cv[a][b] = (dS[pid[a][b]]     / (double)NV  - mi[a]  * mi[b])
                         + (dS[9 + pid[a][b]] / (double)NSV - mu_[a] * mu_[b]);
    }
    __syncthreads();
    if (t < 64) {
        int j = t;
        double w3[3];
        for (int a = 0; a < 3; a++) w3[a] = (double)pw1[a*64 + j];
        double mu = md[0]*w3[0] + md[1]*w3[1] + md[2]*w3[2] + (double)pb1[j];
        double var = 0.0;
        for (int a = 0; a < 3; a++)
            for (int b = 0; b < 3; b++)
                var += w3[a] * Cv[a][b] * w3[b];
        float s = rsqrtf((float)var + EPSF) * pg1[j];
        for (int a = 0; a < 3; a++) g_pweff[a*64 + j] = (float)w3[a] * s;
        g_pweff[192 + j] = (float)((double)pb1[j] - mu) * s + pbe1[j];
    }
}

// ================= fused softmax-scatter + gemm1 + BN stats ================
__global__ void __launch_bounds__(512, 2)
k_sgemm1(const float* __restrict__ feat,
         const float* __restrict__ cw1, const float* __restrict__ cb1) {
    __shared__ float sft[16][CC];
    __shared__ float cfr[CC];
    __shared__ float pred[4][CC];
    int t = threadIdx.x, s = blockIdx.x;
    int wrp = t >> 5, lane = t & 31;

    {
        int row = g_members[s*16 + wrp];
        float4 v = *(const float4*)&feat[row*CC + lane*4];
        float m = fmaxf(fmaxf(v.x, v.y), fmaxf(v.z, v.w));
        for (int o = 16; o; o >>= 1) m = fmaxf(m, __shfl_xor_sync(~0u, m, o));
        float e0 = __expf(v.x - m), e1 = __expf(v.y - m);
        float e2 = __expf(v.z - m), e3 = __expf(v.w - m);
        float sum = e0 + e1 + e2 + e3;
        for (int o = 16; o; o >>= 1) sum += __shfl_xor_sync(~0u, sum, o);
        float inv = 1.f / sum;
        float4 r; r.x = e0*inv; r.y = e1*inv; r.z = e2*inv; r.w = e3*inv;
        *(float4*)&sft[wrp][lane*4] = r;
    }
    __syncthreads();
    if (t < CC) {
        float a = 0.f;
        #pragma unroll
        for (int r = 0; r < 16; r++) a += sft[r][t];
        cfr[t] = a;
    }
    __syncthreads();
    {
        int c = t & (CC-1), ks = t >> 7;
        float acc = 0.f;
        int k0 = ks * 32;
        #pragma unroll 8
        for (int k = k0; k < k0 + 32; k++)
            acc = fmaf(cfr[k], cw1[k*CC + c], acc);
        pred[ks][c] = acc;
    }
    __syncthreads();
    if (t < CC) {
        float v = pred[0][t] + pred[1][t] + pred[2][t] + pred[3][t] + cb1[t];
        g_hid[s*CC + t] = v;
        atomicAdd(&g_acc.s1[t], v);
        atomicAdd(&g_acc.s2[t], v*v);
    }
}

// ================= BN+ReLU + gemm2 + K,V projections (k-split) =============
__global__ void __launch_bounds__(512, 2)
k_gemm2kv(const float* __restrict__ cw2, const float* __restrict__ cb2,
          const float* __restrict__ cg1, const float* __restrict__ cbe1,
          const float* __restrict__ wk,  const float* __restrict__ bk,
          const float* __restrict__ wv,  const float* __restrict__ bv) {
    __shared__ float act[CC], hrow[CC];
    __shared__ float pr[4][CC];
    int t = threadIdx.x, r = blockIdx.x;

    if (t < CC) {
        float mu  = g_acc.s1[t] * (1.f/NSV);
        float var = g_acc.s2[t] * (1.f/NSV) - mu * mu;
        float A = cg1[t] * rsqrtf(var + EPSF);
        float D = cbe1[t] - mu * A;
        act[t] = fmaxf(fmaf(g_hid[r*CC + t], A, D), 0.f);
    }
    __syncthreads();
    {
        int c = t & (CC-1), ks = t >> 7;
        float acc = 0.f;
        int k0 = ks * 32;
        #pragma unroll 8
        for (int k = k0; k < k0 + 32; k++)
            acc = fmaf(act[k], cw2[k*CC + c], acc);
        pr[ks][c] = acc;
    }
    __syncthreads();
    if (t < CC) hrow[t] = pr[0][t] + pr[1][t] + pr[2][t] + pr[3][t] + cb2[t];
    __syncthreads();
    {
        int c = t & (CC-1), sel = t >> 7;
        const float* W = (sel < 2) ? wk : wv;
        int k0 = (sel & 1) * 64;
        float acc = 0.f;
        #pragma unroll 8
        for (int k = k0; k < k0 + 64; k++)
            acc = fmaf(hrow[k], W[k*CC + c], acc);
        pr[sel][c] = acc;
    }
    __syncthreads();
    if (t < 2*CC) {
        int c = t & (CC-1), proj = t >> 7;
        float val = pr[proj*2][c] + pr[proj*2+1][c] + (proj ? bv[c] : bk[c]);
        if (proj) g_v[r*CC + c]   = val;
        else      g_kT[c*NSV + r] = val;
    }
}

// ================= fully fused attention (GQ=8, in-register softmax) =======
// smem float layout (offsets in floats):
//  sfeatT [k][g]   0      .. 1024
//  sqT    [c][g]   1024   .. 2048
//  satt   [h][g][s]2048   .. 18432    (s contiguous; [2048..3072) reused for
//                                      grp1 AV partials after phase-7 reads)
//  spb    [g][s]   18432  .. 20480    (reused as sctxT [c][g] after phase 5)
//  st     [j][g]   20480  .. 20992
//  sw4    [j][4]   20992  .. 21248   {w0,w1,w2,b}
//  spw2   [j]      21248  .. 21312
//  sred            21312  .. 21376
//  spos            21376  .. 21400
#define ATTN_FLOATS 21400
__global__ void __launch_bounds__(256, 2)
k_attn(const int* __restrict__ idx, const float* __restrict__ feat,
       const float* __restrict__ wq, const float* __restrict__ bq,
       const float* __restrict__ wo, const float* __restrict__ bo,
       const float* __restrict__ lng, const float* __restrict__ lnb,
       const float* __restrict__ pw2, const float* __restrict__ pb2) {
    extern __shared__ float sm[];
    float* sfeatT = sm;
    float* sqT    = sm + 1024;
    float* satt   = sm + 2048;
    float* spb    = sm + 18432;
    float* sctxT  = sm + 18432;   // alias: spb dead after phase 5
    float* spart1 = sm + 2048;    // alias: satt[0..1024) dead after phase-7 reads
    float* st     = sm + 20480;
    float* sw4    = sm + 20992;
    float* spw2   = sm + 21248;
    float* sred   = sm + 21312;
    float* spos   = sm + 21376;

    int t = threadIdx.x;
    int n0 = blockIdx.x * GQ;
    int c = t & (CC-1), grp = t >> 7, g0 = grp * 4;

    // ---- phase 1: stage constants + features ----
    { int j = t >> 2, a = t & 3; sw4[t] = g_pweff[a*64 + j]; }
    if (t < 64) spw2[t] = pw2[t];
    if (t < GQ*3) spos[t] = (float)idx[(n0 + t/3)*4 + 1 + (t%3)];
    #pragma unroll
    for (int i = 0; i < 4; i++) {
        int li = t + 256*i;
        sfeatT[(li & (CC-1))*GQ + (li >> 7)] = feat[n0*CC + li];
    }
    __syncthreads();

    // ---- phase 2: t_j(g) table ----
    #pragma unroll
    for (int p = t; p < 64*GQ; p += 256) {
        int j = p >> 3, g = p & 7;
        float4 w = *(const float4*)&sw4[j*4];
        st[p] = fmaf(spos[g*3], w.x, fmaf(spos[g*3+1], w.y, fmaf(spos[g*3+2], w.z, w.w)));
    }
    __syncthreads();

    // ---- phases 3+4 MERGED: q-proj (LDG-bound) + pbias (ALU-bound) ----
    {
        float b = bq[c];
        ull a01 = pk(b, b), a23 = pk(b, b);
        #pragma unroll 4
        for (int k = 0; k < CC; k++) {
            float w = wq[k*CC + c];
            ull wd = pk(w, w);
            float4 f = *(const float4*)&sfeatT[k*GQ + g0];
            FMA2(a01, pk(f.x, f.y), wd, a01);
            FMA2(a23, pk(f.z, f.w), wd, a23);
        }
        float q0,q1,q2,q3;
        upk(q0,q1,a01); upk(q2,q3,a23);
        float4 qo; qo.x = q0*0.25f; qo.y = q1*0.25f; qo.z = q2*0.25f; qo.w = q3*0.25f;
        *(float4*)&sqT[c*GQ + g0] = qo;

        int4 u = g_unq[t];
        float ux = (float)u.y, uy = (float)u.z, uz = (float)u.w;
        float pbv = pb2[0];
        float pb[8];
        #pragma unroll
        for (int g = 0; g < 8; g++) pb[g] = pbv;
        #pragma unroll 2
        for (int j = 0; j < 64; j++) {
            float4 w = *(const float4*)&sw4[j*4];
            float uj = fmaf(ux, w.x, fmaf(uy, w.y, uz * w.z));
            float w2j = spw2[j];
            float4 tA = *(const float4*)&st[j*8];
            float4 tB = *(const float4*)&st[j*8 + 4];
            pb[0] = fmaf(fmaxf(tA.x - uj, 0.f), w2j, pb[0]);
            pb[1] = fmaf(fmaxf(tA.y - uj, 0.f), w2j, pb[1]);
            pb[2] = fmaf(fmaxf(tA.z - uj, 0.f), w2j, pb[2]);
            pb[3] = fmaf(fmaxf(tA.w - uj, 0.f), w2j, pb[3]);
            pb[4] = fmaf(fmaxf(tB.x - uj, 0.f), w2j, pb[4]);
            pb[5] = fmaf(fmaxf(tB.y - uj, 0.f), w2j, pb[5]);
            pb[6] = fmaf(fmaxf(tB.z - uj, 0.f), w2j, pb[6]);
            pb[7] = fmaf(fmaxf(tB.w - uj, 0.f), w2j, pb[7]);
        }
        #pragma unroll
        for (int g = 0; g < 8; g++) spb[g*NSV + t] = pb[g];
    }
    __syncthreads();

    // ---- phase 5: scores + softmax (no max pass; scores provably bounded) -
    // lane mapping s = ln*4 + {0,128}: every warp access spans 512B contiguous
    {
        int h = t >> 5, ln = t & 31;
        int sA = ln * 4, sB = sA + 128;
        ull acc[8][4];     // [g][{A-pair0, A-pair1, B-pair0, B-pair1}]
        #pragma unroll
        for (int g = 0; g < 8; g++) {
            float4 pA = *(const float4*)&spb[g*NSV + sA];
            float4 pB = *(const float4*)&spb[g*NSV + sB];
            acc[g][0] = pk(pA.x, pA.y);
            acc[g][1] = pk(pA.z, pA.w);
            acc[g][2] = pk(pB.x, pB.y);
            acc[g][3] = pk(pB.z, pB.w);
        }
        #pragma unroll 4
        for (int c16 = 0; c16 < DHD; c16++) {
            int cix = h*DHD + c16;
            float4 qA = *(const float4*)&sqT[cix*GQ];
            float4 qB = *(const float4*)&sqT[cix*GQ + 4];
            float4 kA = *(const float4*)&g_kT[cix*NSV + sA];
            float4 kB = *(const float4*)&g_kT[cix*NSV + sB];
            ull kp0 = pk(kA.x, kA.y), kp1 = pk(kA.z, kA.w);
            ull kp2 = pk(kB.x, kB.y), kp3 = pk(kB.z, kB.w);
            float qs[8] = {qA.x,qA.y,qA.z,qA.w,qB.x,qB.y,qB.z,qB.w};
            #pragma unroll
            for (int g = 0; g < 8; g++) {
                ull qd = pk(qs[g], qs[g]);
                FMA2(acc[g][0], kp0, qd, acc[g][0]);
                FMA2(acc[g][1], kp1, qd, acc[g][1]);
                FMA2(acc[g][2], kp2, qd, acc[g][2]);
                FMA2(acc[g][3], kp3, qd, acc[g][3]);
            }
        }
        #pragma unroll
        for (int g = 0; g < 8; g++) {
            float x0,x1,x2,x3,x4,x5,x6,x7;
            upk(x0,x1,acc[g][0]); upk(x2,x3,acc[g][1]);
            upk(x4,x5,acc[g][2]); upk(x6,x7,acc[g][3]);
            x0 = __expf(x0); x1 = __expf(x1);
            x2 = __expf(x2); x3 = __expf(x3);
            x4 = __expf(x4); x5 = __expf(x5);
            x6 = __expf(x6); x7 = __expf(x7);
            float sum = ((x0+x1)+(x2+x3)) + ((x4+x5)+(x6+x7));
            for (int o = 16; o; o >>= 1) sum += __shfl_xor_sync(~0u, sum, o);
            float inv = 1.f / sum;
            float4 w0; w0.x=x0*inv; w0.y=x1*inv; w0.z=x2*inv; w0.w=x3*inv;
            float4 w1; w1.x=x4*inv; w1.y=x5*inv; w1.z=x6*inv; w1.w=x7*inv;
            float* row = &satt[(h*8 + g)*NSV];
            *(float4*)&row[sA] = w0;
            *(float4*)&row[sB] = w1;
        }
    }
    __syncthreads();

    // ---- phase 7: attn @ V — s-range split across grps (half the V LDGs) --
    {
        int hh = c >> 4;
        int sbase = grp * 128;
        const float* abase = &satt[hh*8*NSV + sbase];
        ull A[8];
        #pragma unroll
        for (int g = 0; g < 8; g++) A[g] = 0ull;
        #pragma unroll 4
        for (int s4 = 0; s4 < 32; s4++) {
            int s = s4 * 4;
            const float* vb = &g_v[(sbase + s)*CC + c];
            float v0 = vb[0], v1 = vb[CC], v2 = vb[2*CC], v3 = vb[3*CC];
            ull vlo = pk(v0, v1), vhi = pk(v2, v3);
            #pragma unroll
            for (int g = 0; g < 8; g++) {
                float4 ag = *(const float4*)&abase[g*NSV + s];
                FMA2(A[g], pk(ag.x, ag.y), vlo, A[g]);
                FMA2(A[g], pk(ag.z, ag.w), vhi, A[g]);
            }
        }
        float part[8];
        #pragma unroll
        for (int g = 0; g < 8; g++) {
            float p0, p1;
            upk(p0, p1, A[g]);
            part[g] = p0 + p1;
        }
        __syncthreads();   // all satt reads done; safe to overwrite satt head
        float* dst = grp ? &spart1[c*8] : &sctxT[c*8];
        *(float4*)dst       = *(const float4*)&part[0];
        *(float4*)(dst + 4) = *(const float4*)&part[4];
    }
    __syncthreads();
    // combine halves into sctxT[c][g]
    {
        int cc = t & (CC-1), gh = t >> 7;
        float4 h0 = *(const float4*)&sctxT[cc*8 + gh*4];
        float4 h1 = *(const float4*)&spart1[cc*8 + gh*4];
        float4 cx; cx.x = h0.x + h1.x; cx.y = h0.y + h1.y;
        cx.z = h0.z + h1.z; cx.w = h0.w + h1.w;
        *(float4*)&sctxT[cc*8 + gh*4] = cx;
    }
    __syncthreads();

    // ---- phase 8: o-proj + residual + LayerNorm ----
    {
        float b = bo[c];
        ull a01 = pk(b, b), a23 = pk(b, b);
        #pragma unroll 4
        for (int k = 0; k < CC; k++) {
            float w = wo[k*CC + c];
            ull wd = pk(w, w);
            float4 cx = *(const float4*)&sctxT[k*GQ + g0];
            FMA2(a01, pk(cx.x, cx.y), wd, a01);
            FMA2(a23, pk(cx.z, cx.w), wd, a23);
        }
        float o0,o1,o2,o3;
        upk(o0,o1,a01); upk(o2,o3,a23);
        float yv[4];
        float4 fr = *(const float4*)&sfeatT[c*GQ + g0];
        yv[0] = fr.x + o0; yv[1] = fr.y + o1; yv[2] = fr.z + o2; yv[3] = fr.w + o3;

        int warp = t >> 5, lane = t & 31, w4 = warp & 3;
        #pragma unroll
        for (int gg = 0; gg < 4; gg++) {
            float s = yv[gg], ss = yv[gg]*yv[gg];
            for (int o = 16; o; o >>= 1) {
                s  += __shfl_xor_sync(~0u, s, o);
                ss += __shfl_xor_sync(~0u, ss, o);
            }
            if (lane == 0) {
                sred[(g0+gg)*4 + w4]      = s;
                sred[32 + (g0+gg)*4 + w4] = ss;
            }
        }
        __syncthreads();
        float lg = lng[c], lb = lnb[c];
        #pragma unroll
        for (int gg = 0; gg < 4; gg++) {
            int g = g0 + gg;
            float s  = sred[g*4+0] + sred[g*4+1] + sred[g*4+2] + sred[g*4+3];
            float ss = sred[32+g*4+0] + sred[32+g*4+1] + sred[32+g*4+2] + sred[32+g*4+3];
            float mu = s * (1.f/CC), var = ss * (1.f/CC) - mu*mu;
            g_y[(n0+g)*CC + c] = (yv[gg] - mu) * rsqrtf(var + EPSF) * lg + lb;
        }
    }
}

// ================= submanifold 3^3 conv (float4 y, reg-prefetch W) =========
__global__ void __launch_bounds__(160, 4)
k_conv(const int* __restrict__ idx, const float* __restrict__ segw,
       const float* __restrict__ segb, float* __restrict__ out) {
    __shared__ float sW[CC*NCL];   // 2560 floats
    __shared__ int4 svox[16];
    int t = threadIdx.x;
    int n0 = blockIdx.x * 16;
    if (t < 16) svox[t] = ((const int4*)idx)[n0 + t];

    float4 wr0, wr1, wr2, wr3;
    {
        const float4* src = (const float4*)segw;
        wr0 = src[t]; wr1 = src[t + 160]; wr2 = src[t + 320]; wr3 = src[t + 480];
    }
    __syncthreads();

    int v = t / 10, op = t - v * 10;
    int4 pv = svox[v];
    float2 bb = *(const float2*)&segb[op*2];
    ull acc0 = pk(bb.x, bb.y), acc1 = 0ull;

    for (int d = 0; d < 27; d++) {
        float4* dst = (float4*)sW;
        dst[t] = wr0; dst[t + 160] = wr1; dst[t + 320] = wr2; dst[t + 480] = wr3;
        if (d < 26) {
            const float4* src = (const float4*)&segw[(d+1)*CC*NCL];
            wr0 = src[t]; wr1 = src[t + 160]; wr2 = src[t + 320]; wr3 = src[t + 480];
        }
        __syncthreads();

        int ax = d / 9, ay = (d / 3) % 3, az = d % 3;
        int x = pv.y + ax - 1, y = pv.z + ay - 1, z = pv.w + az - 1;
        if (x >= 0 && x < GXD && y >= 0 && y < GYD && z >= 0 && z < GZD) {
            int m = g_map[((pv.x * GXD + x) * GYD + y) * GZD + z];
            if (m > 0) {
                const float4* yr4 = (const float4*)&g_y[(m-1)*CC];
                const float* wrow = &sW[op*2];
                #pragma unroll 4
                for (int c4 = 0; c4 < CC/4; c4++) {
                    float4 yv = yr4[c4];
                    int cb = c4 * 4 * NCL;
                    FMA2(acc0, pk(yv.x, yv.x), pk2(*(const float2*)&wrow[cb]),         acc0);
                    FMA2(acc1, pk(yv.y, yv.y), pk2(*(const float2*)&wrow[cb + NCL]),   acc1);
                    FMA2(acc0, pk(yv.z, yv.z), pk2(*(const float2*)&wrow[cb + 2*NCL]), acc0);
                    FMA2(acc1, pk(yv.w, yv.w), pk2(*(const float2*)&wrow[cb + 3*NCL]), acc1);
                }
            }
        }
        __syncthreads();
    }
    float a0, a1, b0, b1;
    upk(a0, a1, acc0); upk(b0, b1, acc1);
    float2 res; res.x = a0 + b0; res.y = a1 + b1;
    *(float2*)&out[(n0 + v)*NCL + op*2] = res;
}

// --------------------------------------------------------------------------
extern "C" void kernel_launch(void* const* d_in, const int* in_sizes, int n_in,
                              void* d_out, int out_size) {
    const int*   idx  = (const int*)  d_in[0];
    const float* feat = (const float*)d_in[1];
    const float* cw1  = (const float*)d_in[2];
    const float* cb1  = (const float*)d_in[3];
    const float* cg1  = (const float*)d_in[4];
    const float* cbe1 = (const float*)d_in[5];
    const float* cw2  = (const float*)d_in[6];
    const float* cb2  = (const float*)d_in[7];
    const float* pw1  = (const float*)d_in[8];
    const float* pb1  = (const float*)d_in[9];
    const float* pg1  = (const float*)d_in[10];
    const float* pbe1 = (const float*)d_in[11];
    const float* pw2  = (const float*)d_in[12];
    const float* pb2  = (const float*)d_in[13];
    const float* wq   = (const float*)d_in[14];
    const float* bq   = (const float*)d_in[15];
    const float* wk   = (const float*)d_in[16];
    const float* bk   = (const float*)d_in[17];
    const float* wv   = (const float*)d_in[18];
    const float* bv   = (const float*)d_in[19];
    const float* wo   = (const float*)d_in[20];
    const float* bo   = (const float*)d_in[21];
    const float* ln_g = (const float*)d_in[22];
    const float* ln_b = (const float*)d_in[23];
    const float* segw = (const float*)d_in[24];
    const float* segb = (const float*)d_in[25];

    constexpr int ATTN_SMEM = ATTN_FLOATS * 4;
    cudaFuncSetAttribute(k_attn, cudaFuncAttributeMaxDynamicSharedMemorySize, ATTN_SMEM);

    k_prep    <<<1, 256>>>(idx, pw1, pb1, pg1, pbe1);
    k_sgemm1  <<<NSV, 512>>>(feat, cw1, cb1);
    k_gemm2kv <<<NSV, 512>>>(cw2, cb2, cg1, cbe1, wk, bk, wv, bv);
    k_attn    <<<NV/GQ, 256, ATTN_SMEM>>>(idx, feat, wq, bq, wo, bo, ln_g, ln_b, pw2, pb2);
    k_conv    <<<NV/16, 160>>>(idx, segw, segb, (float*)d_out);
}

// round 14
// speedup vs baseline: 1.0090x; 1.0090x over previous
#include <cuda_runtime.h>
#include <cuda_fp16.h>

#define NV   4096
#define NSV  256
#define BB   2
#define GXD  128
#define GYD  128
#define GZD  16
#define CC   128
#define NCL  20
#define NH   8
#define DHD  16
#define MAPSZ (BB*GXD*GYD*GZD)
#define EPSF 1e-5f
#define GQ   8

// ---------------- packed f32x2 helpers ----------------
typedef unsigned long long ull;
__device__ __forceinline__ ull pk(float lo, float hi) {
    ull r; asm("mov.b64 %0, {%1,%2};" : "=l"(r) : "f"(lo), "f"(hi)); return r;
}
__device__ __forceinline__ ull pk2(float2 f) { return pk(f.x, f.y); }
__device__ __forceinline__ void upk(float& lo, float& hi, ull v) {
    asm("mov.b64 {%0,%1}, %2;" : "=f"(lo), "=f"(hi) : "l"(v));
}
#define FMA2(d,a,b,c) asm("fma.rn.f32x2 %0, %1, %2, %3;" : "=l"(d) : "l"(a), "l"(b), "l"(c))

// ---------------- device scratch ----------------
struct Acc { float s1[CC]; float s2[CC]; };
__device__ Acc  g_acc;
__device__ int4 g_unq[NSV];
__device__ int  g_members[NSV*16];
__device__ float g_hid[NSV*CC];
__device__ float g_kT[CC*NSV];     // K transposed [c][s]
__device__ float g_v[NSV*CC];      // V natural    [s][c]
__device__ float g_y[NV*CC];
__device__ int   g_map[MAPSZ];     // zero-init; stores n+1 (idempotent per input)
__device__ float g_pweff[4*64];

// ================= k_prep: zero acc, keys, unique, members, pbias fold ====
__global__ void k_prep(const int* __restrict__ idx,
                       const float* __restrict__ pw1, const float* __restrict__ pb1,
                       const float* __restrict__ pg1, const float* __restrict__ pbe1) {
    __shared__ unsigned sflags[256];
    __shared__ unsigned short skeys[NV];
    __shared__ int sscan[256], srank[256], scnt[256];
    __shared__ double dS[18];              // Si[0..9), Su[9..18)
    __shared__ double md[3], Cv[3][3];
    int t = threadIdx.x, lane = t & 31;

    if (t < 128) g_acc.s1[t] = 0.f; else g_acc.s2[t & 127] = 0.f;
    if (t < 18) dS[t] = 0.0;

    sflags[t] = 0u;
    scnt[t] = 0;
    __syncthreads();

    long long m[9] = {0,0,0,0,0,0,0,0,0};
    for (int i = t; i < NV; i += 256) {
        int4 p = ((const int4*)idx)[i];
        int key = ((p.x * 32 + (p.y >> 2)) * 32 + (p.z >> 2)) * 4 + (p.w >> 2);
        skeys[i] = (unsigned short)key;
        atomicOr(&sflags[key >> 5], 1u << (key & 31));
        g_map[((p.x * GXD + p.y) * GYD + p.z) * GZD + p.w] = i + 1;
        long long xs = p.y, ys = p.z, zs = p.w;
        m[0]+=xs; m[1]+=ys; m[2]+=zs; m[3]+=xs*xs; m[4]+=ys*ys; m[5]+=zs*zs;
        m[6]+=xs*ys; m[7]+=xs*zs; m[8]+=ys*zs;
    }
    __syncthreads();

    unsigned w = sflags[t];
    int cnt = __popc(w);
    sscan[t] = cnt; __syncthreads();
    for (int off = 1; off < 256; off <<= 1) {
        int v = (t >= off) ? sscan[t - off] : 0;
        __syncthreads(); sscan[t] += v; __syncthreads();
    }
    int excl = sscan[t] - cnt;
    srank[t] = excl;
    unsigned wb = w;
    while (wb) {
        int bit = __ffs(wb) - 1; wb &= wb - 1;
        int rank = excl + __popc(w & ((1u << bit) - 1u));
        int key = t * 32 + bit;
        int4 u;
        u.w = key & 3; u.z = (key >> 2) & 31; u.y = (key >> 7) & 31; u.x = key >> 12;
        g_unq[rank] = u;
    }
    __syncthreads();

    for (int i = t; i < NV; i += 256) {
        int key = skeys[i];
        int s = srank[key >> 5] + __popc(sflags[key >> 5] & ((1u << (key & 31)) - 1u));
        int slot = atomicAdd(&scnt[s], 1);
        g_members[s*16 + slot] = i;
    }
    #pragma unroll
    for (int k = 0; k < 9; k++) {
        long long v = m[k];
        for (int o = 16; o; o >>= 1) v += __shfl_xor_sync(~0u, v, o);
        if (lane == 0) atomicAdd(&dS[k], (double)v);
    }
    {
        int4 u = g_unq[t];
        long long xs = u.y, ys = u.z, zs = u.w;
        long long mu9[9] = { xs, ys, zs, xs*xs, ys*ys, zs*zs, xs*ys, xs*zs, ys*zs };
        #pragma unroll
        for (int k = 0; k < 9; k++) {
            long long v = mu9[k];
            for (int o = 16; o; o >>= 1) v += __shfl_xor_sync(~0u, v, o);
            if (lane == 0) atomicAdd(&dS[9 + k], (double)v);
        }
    }
    __syncthreads();

    if (t == 0) {
        double mi[3], mu_[3];
        for (int a = 0; a < 3; a++) {
            mi[a]  = dS[a]     / (double)NV;
            mu_[a] = dS[9 + a] / (double)NSV;
            md[a]  = mi[a] - mu_[a];
        }
        const int pid[3][3] = { {3,6,7}, {6,4,8}, {7,8,5} };
        for (int a = 0; a < 3; a++)
            for (int b = 0; b < 3; b++)
                Cv[a][b] = (dS[pid[a][b]]     / (double)NV  - mi[a]  * mi[b])
                         + (dS[9 + pid[a][b]] / (double)NSV - mu_[a] * mu_[b]);
    }
    __syncthreads();
    if (t < 64) {
        int j = t;
        double w3[3];
        for (int a = 0; a < 3; a++) w3[a] = (double)pw1[a*64 + j];
        double mu = md[0]*w3[0] + md[1]*w3[1] + md[2]*w3[2] + (double)pb1[j];
        double var = 0.0;
        for (int a = 0; a < 3; a++)
            for (int b = 0; b < 3; b++)
                var += w3[a] * Cv[a][b] * w3[b];
        float s = rsqrtf((float)var + EPSF) * pg1[j];
        for (int a = 0; a < 3; a++) g_pweff[a*64 + j] = (float)w3[a] * s;
        g_pweff[192 + j] = (float)((double)pb1[j] - mu) * s + pbe1[j];
    }
}

// ================= fused softmax-scatter + gemm1 + BN stats ================
__global__ void __launch_bounds__(512, 2)
k_sgemm1(const float* __restrict__ feat,
         const float* __restrict__ cw1, const float* __restrict__ cb1) {
    __shared__ float sft[16][CC];
    __shared__ float cfr[CC];
    __shared__ float pred[4][CC];
    int t = threadIdx.x, s = blockIdx.x;
    int wrp = t >> 5, lane = t & 31;

    {
        int row = g_members[s*16 + wrp];
        float4 v = *(const float4*)&feat[row*CC + lane*4];
        float m = fmaxf(fmaxf(v.x, v.y), fmaxf(v.z, v.w));
        for (int o = 16; o; o >>= 1) m = fmaxf(m, __shfl_xor_sync(~0u, m, o));
        float e0 = __expf(v.x - m), e1 = __expf(v.y - m);
        float e2 = __expf(v.z - m), e3 = __expf(v.w - m);
        float sum = e0 + e1 + e2 + e3;
        for (int o = 16; o; o >>= 1) sum += __shfl_xor_sync(~0u, sum, o);
        float inv = 1.f / sum;
        float4 r; r.x = e0*inv; r.y = e1*inv; r.z = e2*inv; r.w = e3*inv;
        *(float4*)&sft[wrp][lane*4] = r;
    }
    __syncthreads();
    if (t < CC) {
        float a = 0.f;
        #pragma unroll
        for (int r = 0; r < 16; r++) a += sft[r][t];
        cfr[t] = a;
    }
    __syncthreads();
    {
        int c = t & (CC-1), ks = t >> 7;
        float acc = 0.f;
        int k0 = ks * 32;
        #pragma unroll 8
        for (int k = k0; k < k0 + 32; k++)
            acc = fmaf(cfr[k], cw1[k*CC + c], acc);
        pred[ks][c] = acc;
    }
    __syncthreads();
    if (t < CC) {
        float v = pred[0][t] + pred[1][t] + pred[2][t] + pred[3][t] + cb1[t];
        g_hid[s*CC + t] = v;
        atomicAdd(&g_acc.s1[t], v);
        atomicAdd(&g_acc.s2[t], v*v);
    }
}

// ================= BN+ReLU + gemm2 + K,V projections (k-split) =============
__global__ void __launch_bounds__(512, 2)
k_gemm2kv(const float* __restrict__ cw2, const float* __restrict__ cb2,
          const float* __restrict__ cg1, const float* __restrict__ cbe1,
          const float* __restrict__ wk,  const float* __restrict__ bk,
          const float* __restrict__ wv,  const float* __restrict__ bv) {
    __shared__ float act[CC], hrow[CC];
    __shared__ float pr[4][CC];
    int t = threadIdx.x, r = blockIdx.x;

    if (t < CC) {
        float mu  = g_acc.s1[t] * (1.f/NSV);
        float var = g_acc.s2[t] * (1.f/NSV) - mu * mu;
        float A = cg1[t] * rsqrtf(var + EPSF);
        float D = cbe1[t] - mu * A;
        act[t] = fmaxf(fmaf(g_hid[r*CC + t], A, D), 0.f);
    }
    __syncthreads();
    {
        int c = t & (CC-1), ks = t >> 7;
        float acc = 0.f;
        int k0 = ks * 32;
        #pragma unroll 8
        for (int k = k0; k < k0 + 32; k++)
            acc = fmaf(act[k], cw2[k*CC + c], acc);
        pr[ks][c] = acc;
    }
    __syncthreads();
    if (t < CC) hrow[t] = pr[0][t] + pr[1][t] + pr[2][t] + pr[3][t] + cb2[t];
    __syncthreads();
    {
        int c = t & (CC-1), sel = t >> 7;
        const float* W = (sel < 2) ? wk : wv;
        int k0 = (sel & 1) * 64;
        float acc = 0.f;
        #pragma unroll 8
        for (int k = k0; k < k0 + 64; k++)
            acc = fmaf(hrow[k], W[k*CC + c], acc);
        pr[sel][c] = acc;
    }
    __syncthreads();
    if (t < 2*CC) {
        int c = t & (CC-1), proj = t >> 7;
        float val = pr[proj*2][c] + pr[proj*2+1][c] + (proj ? bv[c] : bk[c]);
        if (proj) g_v[r*CC + c]   = val;
        else      g_kT[c*NSV + r] = val;
    }
}

// ================= fully fused attention (fp16 satt, 3 blocks/SM) ==========
// smem float layout (offsets in floats):
//  sfeatT [k][g]   0      .. 1024
//  sqT    [c][g]   1024   .. 2048
//  satt_h [h][g][s]2048   .. 10240   (fp16! 64 rows x 256 halves = 32 KB;
//                                     first 1024 floats reused for grp1 partials)
//  spb    [g][s]   10240  .. 12288   (reused as sctxT [c][g] after phase 5)
//  st     [j][g]   12288  .. 12800
//  sw4    [j][4]   12800  .. 13056   {w0,w1,w2,b}
//  spw2   [j]      13056  .. 13120
//  sred            13120  .. 13184
//  spos            13184  .. 13208
#define ATTN_FLOATS 13208
__global__ void __launch_bounds__(256, 3)
k_attn(const int* __restrict__ idx, const float* __restrict__ feat,
       const float* __restrict__ wq, const float* __restrict__ bq,
       const float* __restrict__ wo, const float* __restrict__ bo,
       const float* __restrict__ lng, const float* __restrict__ lnb,
       const float* __restrict__ pw2, const float* __restrict__ pb2) {
    extern __shared__ float sm[];
    float*  sfeatT = sm;
    float*  sqT    = sm + 1024;
    __half* satt_h = (__half*)(sm + 2048);
    float*  spart1 = sm + 2048;   // alias: satt head dead after phase-7 reads
    float*  spb    = sm + 10240;
    float*  sctxT  = sm + 10240;  // alias: spb dead after phase 5
    float*  st     = sm + 12288;
    float*  sw4    = sm + 12800;
    float*  spw2   = sm + 13056;
    float*  sred   = sm + 13120;
    float*  spos   = sm + 13184;

    int t = threadIdx.x;
    int n0 = blockIdx.x * GQ;
    int c = t & (CC-1), grp = t >> 7, g0 = grp * 4;

    // ---- phase 1: stage constants + features ----
    { int j = t >> 2, a = t & 3; sw4[t] = g_pweff[a*64 + j]; }
    if (t < 64) spw2[t] = pw2[t];
    if (t < GQ*3) spos[t] = (float)idx[(n0 + t/3)*4 + 1 + (t%3)];
    #pragma unroll
    for (int i = 0; i < 4; i++) {
        int li = t + 256*i;
        sfeatT[(li & (CC-1))*GQ + (li >> 7)] = feat[n0*CC + li];
    }
    __syncthreads();

    // ---- phase 2: t_j(g) table ----
    #pragma unroll
    for (int p = t; p < 64*GQ; p += 256) {
        int j = p >> 3, g = p & 7;
        float4 w = *(const float4*)&sw4[j*4];
        st[p] = fmaf(spos[g*3], w.x, fmaf(spos[g*3+1], w.y, fmaf(spos[g*3+2], w.z, w.w)));
    }
    __syncthreads();

    // ---- phases 3+4 MERGED: q-proj (LDG-bound) + pbias (ALU-bound) ----
    {
        float b = bq[c];
        ull a01 = pk(b, b), a23 = pk(b, b);
        #pragma unroll 4
        for (int k = 0; k < CC; k++) {
            float w = wq[k*CC + c];
            ull wd = pk(w, w);
            float4 f = *(const float4*)&sfeatT[k*GQ + g0];
            FMA2(a01, pk(f.x, f.y), wd, a01);
            FMA2(a23, pk(f.z, f.w), wd, a23);
        }
        float q0,q1,q2,q3;
        upk(q0,q1,a01); upk(q2,q3,a23);
        float4 qo; qo.x = q0*0.25f; qo.y = q1*0.25f; qo.z = q2*0.25f; qo.w = q3*0.25f;
        *(float4*)&sqT[c*GQ + g0] = qo;

        int4 u = g_unq[t];
        float ux = (float)u.y, uy = (float)u.z, uz = (float)u.w;
        float pbv = pb2[0];
        float pb[8];
        #pragma unroll
        for (int g = 0; g < 8; g++) pb[g] = pbv;
        #pragma unroll 2
        for (int j = 0; j < 64; j++) {
            float4 w = *(const float4*)&sw4[j*4];
            float uj = fmaf(ux, w.x, fmaf(uy, w.y, uz * w.z));
            float w2j = spw2[j];
            float4 tA = *(const float4*)&st[j*8];
            float4 tB = *(const float4*)&st[j*8 + 4];
            pb[0] = fmaf(fmaxf(tA.x - uj, 0.f), w2j, pb[0]);
            pb[1] = fmaf(fmaxf(tA.y - uj, 0.f), w2j, pb[1]);
            pb[2] = fmaf(fmaxf(tA.z - uj, 0.f), w2j, pb[2]);
            pb[3] = fmaf(fmaxf(tA.w - uj, 0.f), w2j, pb[3]);
            pb[4] = fmaf(fmaxf(tB.x - uj, 0.f), w2j, pb[4]);
            pb[5] = fmaf(fmaxf(tB.y - uj, 0.f), w2j, pb[5]);
            pb[6] = fmaf(fmaxf(tB.z - uj, 0.f), w2j, pb[6]);
            pb[7] = fmaf(fmaxf(tB.w - uj, 0.f), w2j, pb[7]);
        }
        #pragma unroll
        for (int g = 0; g < 8; g++) spb[g*NSV + t] = pb[g];
    }
    __syncthreads();

    // ---- phase 5: scores + softmax (no max pass), two g-halves for regs ---
    // lane mapping s = ln*4 + {0,128}; satt stored as fp16
    {
        int h = t >> 5, ln = t & 31;
        int sA = ln * 4, sB = sA + 128;
        #pragma unroll
        for (int gh = 0; gh < 2; gh++) {
            ull acc[4][4];
            #pragma unroll
            for (int g = 0; g < 4; g++) {
                float4 pA = *(const float4*)&spb[(gh*4 + g)*NSV + sA];
                float4 pB = *(const float4*)&spb[(gh*4 + g)*NSV + sB];
                acc[g][0] = pk(pA.x, pA.y);
                acc[g][1] = pk(pA.z, pA.w);
                acc[g][2] = pk(pB.x, pB.y);
                acc[g][3] = pk(pB.z, pB.w);
            }
            #pragma unroll 4
            for (int c16 = 0; c16 < DHD; c16++) {
                int cix = h*DHD + c16;
                float4 qA = *(const float4*)&sqT[cix*GQ + gh*4];
                float4 kA = *(const float4*)&g_kT[cix*NSV + sA];
                float4 kB = *(const float4*)&g_kT[cix*NSV + sB];
                ull kp0 = pk(kA.x, kA.y), kp1 = pk(kA.z, kA.w);
                ull kp2 = pk(kB.x, kB.y), kp3 = pk(kB.z, kB.w);
                float qs[4] = {qA.x, qA.y, qA.z, qA.w};
                #pragma unroll
                for (int g = 0; g < 4; g++) {
                    ull qd = pk(qs[g], qs[g]);
                    FMA2(acc[g][0], kp0, qd, acc[g][0]);
                    FMA2(acc[g][1], kp1, qd, acc[g][1]);
                    FMA2(acc[g][2], kp2, qd, acc[g][2]);
                    FMA2(acc[g][3], kp3, qd, acc[g][3]);
                }
            }
            #pragma unroll
            for (int g = 0; g < 4; g++) {
                float x0,x1,x2,x3,x4,x5,x6,x7;
                upk(x0,x1,acc[g][0]); upk(x2,x3,acc[g][1]);
                upk(x4,x5,acc[g][2]); upk(x6,x7,acc[g][3]);
                x0 = __expf(x0); x1 = __expf(x1);
                x2 = __expf(x2); x3 = __expf(x3);
                x4 = __expf(x4); x5 = __expf(x5);
                x6 = __expf(x6); x7 = __expf(x7);
                float sum = ((x0+x1)+(x2+x3)) + ((x4+x5)+(x6+x7));
                for (int o = 16; o; o >>= 1) sum += __shfl_xor_sync(~0u, sum, o);
                float inv = 1.f / sum;
                __half* row = &satt_h[(h*8 + gh*4 + g)*NSV];
                *(__half2*)&row[sA]     = __floats2half2_rn(x0*inv, x1*inv);
                *(__half2*)&row[sA + 2] = __floats2half2_rn(x2*inv, x3*inv);
                *(__half2*)&row[sB]     = __floats2half2_rn(x4*inv, x5*inv);
                *(__half2*)&row[sB + 2] = __floats2half2_rn(x6*inv, x7*inv);
            }
        }
    }
    __syncthreads();

    // ---- phase 7: attn @ V — s-range split across grps, fp16 a rows ------
    {
        int hh = c >> 4;
        int sbase = grp * 128;
        const __half* abase = &satt_h[hh*8*NSV + sbase];
        ull A[8];
        #pragma unroll
        for (int g = 0; g < 8; g++) A[g] = 0ull;
        #pragma unroll 4
        for (int s4 = 0; s4 < 32; s4++) {
            int s = s4 * 4;
            const float* vb = &g_v[(sbase + s)*CC + c];
            float v0 = vb[0], v1 = vb[CC], v2 = vb[2*CC], v3 = vb[3*CC];
            ull vlo = pk(v0, v1), vhi = pk(v2, v3);
            #pragma unroll
            for (int g = 0; g < 8; g++) {
                __half2 h01 = *(const __half2*)&abase[g*NSV + s];
                __half2 h23 = *(const __half2*)&abase[g*NSV + s + 2];
                float2 f01 = __half22float2(h01);
                float2 f23 = __half22float2(h23);
                FMA2(A[g], pk2(f01), vlo, A[g]);
                FMA2(A[g], pk2(f23), vhi, A[g]);
            }
        }
        float part[8];
        #pragma unroll
        for (int g = 0; g < 8; g++) {
            float p0, p1;
            upk(p0, p1, A[g]);
            part[g] = p0 + p1;
        }
        __syncthreads();   // all satt reads done; safe to overwrite satt head
        float* dst = grp ? &spart1[c*8] : &sctxT[c*8];
        *(float4*)dst       = *(const float4*)&part[0];
        *(float4*)(dst + 4) = *(const float4*)&part[4];
    }
    __syncthreads();
    // combine halves into sctxT[c][g]
    {
        int cc = t & (CC-1), gh = t >> 7;
        float4 h0 = *(const float4*)&sctxT[cc*8 + gh*4];
        float4 h1 = *(const float4*)&spart1[cc*8 + gh*4];
        float4 cx; cx.x = h0.x + h1.x; cx.y = h0.y + h1.y;
        cx.z = h0.z + h1.z; cx.w = h0.w + h1.w;
        *(float4*)&sctxT[cc*8 + gh*4] = cx;
    }
    __syncthreads();

    // ---- phase 8: o-proj + residual + LayerNorm ----
    {
        float b = bo[c];
        ull a01 = pk(b, b), a23 = pk(b, b);
        #pragma unroll 4
        for (int k = 0; k < CC; k++) {
            float w = wo[k*CC + c];
            ull wd = pk(w, w);
            float4 cx = *(const float4*)&sctxT[k*GQ + g0];
            FMA2(a01, pk(cx.x, cx.y), wd, a01);
            FMA2(a23, pk(cx.z, cx.w), wd, a23);
        }
        float o0,o1,o2,o3;
        upk(o0,o1,a01); upk(o2,o3,a23);
        float yv[4];
        float4 fr = *(const float4*)&sfeatT[c*GQ + g0];
        yv[0] = fr.x + o0; yv[1] = fr.y + o1; yv[2] = fr.z + o2; yv[3] = fr.w + o3;

        int warp = t >> 5, lane = t & 31, w4 = warp & 3;
        #pragma unroll
        for (int gg = 0; gg < 4; gg++) {
            float s = yv[gg], ss = yv[gg]*yv[gg];
            for (int o = 16; o; o >>= 1) {
                s  += __shfl_xor_sync(~0u, s, o);
                ss += __shfl_xor_sync(~0u, ss, o);
            }
            if (lane == 0) {
                sred[(g0+gg)*4 + w4]      = s;
                sred[32 + (g0+gg)*4 + w4] = ss;
            }
        }
        __syncthreads();
        float lg = lng[c], lb = lnb[c];
        #pragma unroll
        for (int gg = 0; gg < 4; gg++) {
            int g = g0 + gg;
            float s  = sred[g*4+0] + sred[g*4+1] + sred[g*4+2] + sred[g*4+3];
            float ss = sred[32+g*4+0] + sred[32+g*4+1] + sred[32+g*4+2] + sred[32+g*4+3];
            float mu = s * (1.f/CC), var = ss * (1.f/CC) - mu*mu;
            g_y[(n0+g)*CC + c] = (yv[gg] - mu) * rsqrtf(var + EPSF) * lg + lb;
        }
    }
}

// ================= submanifold 3^3 conv (float4 y, reg-prefetch W) =========
__global__ void __launch_bounds__(160, 4)
k_conv(const int* __restrict__ idx, const float* __restrict__ segw,
       const float* __restrict__ segb, float* __restrict__ out) {
    __shared__ float sW[CC*NCL];   // 2560 floats
    __shared__ int4 svox[16];
    int t = threadIdx.x;
    int n0 = blockIdx.x * 16;
    if (t < 16) svox[t] = ((const int4*)idx)[n0 + t];

    float4 wr0, wr1, wr2, wr3;
    {
        const float4* src = (const float4*)segw;
        wr0 = src[t]; wr1 = src[t + 160]; wr2 = src[t + 320]; wr3 = src[t + 480];
    }
    __syncthreads();

    int v = t / 10, op = t - v * 10;
    int4 pv = svox[v];
    float2 bb = *(const float2*)&segb[op*2];
    ull acc0 = pk(bb.x, bb.y), acc1 = 0ull;

    for (int d = 0; d < 27; d++) {
        float4* dst = (float4*)sW;
        dst[t] = wr0; dst[t + 160] = wr1; dst[t + 320] = wr2; dst[t + 480] = wr3;
        if (d < 26) {
            const float4* src = (const float4*)&segw[(d+1)*CC*NCL];
            wr0 = src[t]; wr1 = src[t + 160]; wr2 = src[t + 320]; wr3 = src[t + 480];
        }
        __syncthreads();

        int ax = d / 9, ay = (d / 3) % 3, az = d % 3;
        int x = pv.y + ax - 1, y = pv.z + ay - 1, z = pv.w + az - 1;
        if (x >= 0 && x < GXD && y >= 0 && y < GYD && z >= 0 && z < GZD) {
            int m = g_map[((pv.x * GXD + x) * GYD + y) * GZD + z];
            if (m > 0) {
                const float4* yr4 = (const float4*)&g_y[(m-1)*CC];
                const float* wrow = &sW[op*2];
                #pragma unroll 4
                for (int c4 = 0; c4 < CC/4; c4++) {
                    float4 yv = yr4[c4];
                    int cb = c4 * 4 * NCL;
                    FMA2(acc0, pk(yv.x, yv.x), pk2(*(const float2*)&wrow[cb]),         acc0);
                    FMA2(acc1, pk(yv.y, yv.y), pk2(*(const float2*)&wrow[cb + NCL]),   acc1);
                    FMA2(acc0, pk(yv.z, yv.z), pk2(*(const float2*)&wrow[cb + 2*NCL]), acc0);
                    FMA2(acc1, pk(yv.w, yv.w), pk2(*(const float2*)&wrow[cb + 3*NCL]), acc1);
                }
            }
        }
        __syncthreads();
    }
    float a0, a1, b0, b1;
    upk(a0, a1, acc0); upk(b0, b1, acc1);
    float2 res; res.x = a0 + b0; res.y = a1 + b1;
    *(float2*)&out[(n0 + v)*NCL + op*2] = res;
}

// --------------------------------------------------------------------------
extern "C" void kernel_launch(void* const* d_in, const int* in_sizes, int n_in,
                              void* d_out, int out_size) {
    const int*   idx  = (const int*)  d_in[0];
    const float* feat = (const float*)d_in[1];
    const float* cw1  = (const float*)d_in[2];
    const float* cb1  = (const float*)d_in[3];
    const float* cg1  = (const float*)d_in[4];
    const float* cbe1 = (const float*)d_in[5];
    const float* cw2  = (const float*)d_in[6];
    const float* cb2  = (const float*)d_in[7];
    const float* pw1  = (const float*)d_in[8];
    const float* pb1  = (const float*)d_in[9];
    const float* pg1  = (const float*)d_in[10];
    const float* pbe1 = (const float*)d_in[11];
    const float* pw2  = (const float*)d_in[12];
    const float* pb2  = (const float*)d_in[13];
    const float* wq   = (const float*)d_in[14];
    const float* bq   = (const float*)d_in[15];
    const float* wk   = (const float*)d_in[16];
    const float* bk   = (const float*)d_in[17];
    const float* wv   = (const float*)d_in[18];
    const float* bv   = (const float*)d_in[19];
    const float* wo   = (const float*)d_in[20];
    const float* bo   = (const float*)d_in[21];
    const float* ln_g = (const float*)d_in[22];
    const float* ln_b = (const float*)d_in[23];
    const float* segw = (const float*)d_in[24];
    const float* segb = (const float*)d_in[25];

    constexpr int ATTN_SMEM = ATTN_FLOATS * 4;
    cudaFuncSetAttribute(k_attn, cudaFuncAttributeMaxDynamicSharedMemorySize, ATTN_SMEM);

    k_prep    <<<1, 256>>>(idx, pw1, pb1, pg1, pbe1);
    k_sgemm1  <<<NSV, 512>>>(feat, cw1, cb1);
    k_gemm2kv <<<NSV, 512>>>(cw2, cb2, cg1, cbe1, wk, bk, wv, bv);
    k_attn    <<<NV/GQ, 256, ATTN_SMEM>>>(idx, feat, wq, bq, wo, bo, ln_g, ln_b, pw2, pb2);
    k_conv    <<<NV/16, 160>>>(idx, segw, segb, (float*)d_out);
}

// round 15
// speedup vs baseline: 1.0219x; 1.0128x over previous
#include <cuda_runtime.h>
#include <cuda_fp16.h>

#define NV   4096
#define NSV  256
#define BB   2
#define GXD  128
#define GYD  128
#define GZD  16
#define CC   128
#define NCL  20
#define NH   8
#define DHD  16
#define MAPSZ (BB*GXD*GYD*GZD)
#define EPSF 1e-5f
#define GQ   8

// ---------------- packed f32x2 helpers ----------------
typedef unsigned long long ull;
__device__ __forceinline__ ull pk(float lo, float hi) {
    ull r; asm("mov.b64 %0, {%1,%2};" : "=l"(r) : "f"(lo), "f"(hi)); return r;
}
__device__ __forceinline__ ull pk2(float2 f) { return pk(f.x, f.y); }
__device__ __forceinline__ void upk(float& lo, float& hi, ull v) {
    asm("mov.b64 {%0,%1}, %2;" : "=f"(lo), "=f"(hi) : "l"(v));
}
#define FMA2(d,a,b,c) asm("fma.rn.f32x2 %0, %1, %2, %3;" : "=l"(d) : "l"(a), "l"(b), "l"(c))

// ---------------- device scratch ----------------
struct Acc { float s1[CC]; float s2[CC]; };
__device__ Acc  g_acc;
__device__ int4 g_unq[NSV];
__device__ int  g_members[NSV*16];
__device__ float g_hid[NSV*CC];
__device__ float g_kT[CC*NSV];     // K transposed [c][s]
__device__ float g_v[NSV*CC];      // V natural    [s][c]
__device__ float g_y[NV*CC];
__device__ int   g_map[MAPSZ];     // zero-init; stores n+1 (idempotent per input)
__device__ float g_pweff[4*64];

// ================= k_prep: zero acc, keys, unique, members, pbias fold ====
__global__ void k_prep(const int* __restrict__ idx,
                       const float* __restrict__ pw1, const float* __restrict__ pb1,
                       const float* __restrict__ pg1, const float* __restrict__ pbe1) {
    __shared__ unsigned sflags[256];
    __shared__ unsigned short skeys[NV];
    __shared__ int sscan[256], srank[256], scnt[256];
    __shared__ double dS[18];
    __shared__ double md[3], Cv[3][3];
    int t = threadIdx.x, lane = t & 31;

    if (t < 128) g_acc.s1[t] = 0.f; else g_acc.s2[t & 127] = 0.f;
    if (t < 18) dS[t] = 0.0;

    sflags[t] = 0u;
    scnt[t] = 0;
    __syncthreads();

    long long m[9] = {0,0,0,0,0,0,0,0,0};
    for (int i = t; i < NV; i += 256) {
        int4 p = ((const int4*)idx)[i];
        int key = ((p.x * 32 + (p.y >> 2)) * 32 + (p.z >> 2)) * 4 + (p.w >> 2);
        skeys[i] = (unsigned short)key;
        atomicOr(&sflags[key >> 5], 1u << (key & 31));
        g_map[((p.x * GXD + p.y) * GYD + p.z) * GZD + p.w] = i + 1;
        long long xs = p.y, ys = p.z, zs = p.w;
        m[0]+=xs; m[1]+=ys; m[2]+=zs; m[3]+=xs*xs; m[4]+=ys*ys; m[5]+=zs*zs;
        m[6]+=xs*ys; m[7]+=xs*zs; m[8]+=ys*zs;
    }
    __syncthreads();

    unsigned w = sflags[t];
    int cnt = __popc(w);
    sscan[t] = cnt; __syncthreads();
    for (int off = 1; off < 256; off <<= 1) {
        int v = (t >= off) ? sscan[t - off] : 0;
        __syncthreads(); sscan[t] += v; __syncthreads();
    }
    int excl = sscan[t] - cnt;
    srank[t] = excl;
    unsigned wb = w;
    while (wb) {
        int bit = __ffs(wb) - 1; wb &= wb - 1;
        int rank = excl + __popc(w & ((1u << bit) - 1u));
        int key = t * 32 + bit;
        int4 u;
        u.w = key & 3; u.z = (key >> 2) & 31; u.y = (key >> 7) & 31; u.x = key >> 12;
        g_unq[rank] = u;
    }
    __syncthreads();

    for (int i = t; i < NV; i += 256) {
        int key = skeys[i];
        int s = srank[key >> 5] + __popc(sflags[key >> 5] & ((1u << (key & 31)) - 1u));
        int slot = atomicAdd(&scnt[s], 1);
        g_members[s*16 + slot] = i;
    }
    #pragma unroll
    for (int k = 0; k < 9; k++) {
        long long v = m[k];
        for (int o = 16; o; o >>= 1) v += __shfl_xor_sync(~0u, v, o);
        if (lane == 0) atomicAdd(&dS[k], (double)v);
    }
    {
        int4 u = g_unq[t];
        long long xs = u.y, ys = u.z, zs = u.w;
        long long mu9[9] = { xs, ys, zs, xs*xs, ys*ys, zs*zs, xs*ys, xs*zs, ys*zs };
        #pragma unroll
        for (int k = 0; k < 9; k++) {
            long long v = mu9[k];
            for (int o = 16; o; o >>= 1) v += __shfl_xor_sync(~0u, v, o);
            if (lane == 0) atomicAdd(&dS[9 + k], (double)v);
        }
    }
    __syncthreads();

    if (t == 0) {
        double mi[3], mu_[3];
        for (int a = 0; a < 3; a++) {
            mi[a]  = dS[a]     / (double)NV;
            mu_[a] = dS[9 + a] / (double)NSV;
            md[a]  = mi[a] - mu_[a];
        }
        const int pid[3][3] = { {3,6,7}, {6,4,8}, {7,8,5} };
        for (int a = 0; a < 3; a++)
            for (int b = 0; b < 3; b++)
                Cv[a][b] = (dS[pid[a][b]]     / (double)NV  - mi[a]  * mi[b])
                         + (dS[9 + pid[a][b]] / (double)NSV - mu_[a] * mu_[b]);
    }
    __syncthreads();
    if (t < 64) {
        int j = t;
        double w3[3];
        for (int a = 0; a < 3; a++) w3[a] = (double)pw1[a*64 + j];
        double mu = md[0]*w3[0] + md[1]*w3[1] + md[2]*w3[2] + (double)pb1[j];
        double var = 0.0;
        for (int a = 0; a < 3; a++)
            for (int b = 0; b < 3; b++)
                var += w3[a] * Cv[a][b] * w3[b];
        float s = rsqrtf((float)var + EPSF) * pg1[j];
        for (int a = 0; a < 3; a++) g_pweff[a*64 + j] = (float)w3[a] * s;
        g_pweff[192 + j] = (float)((double)pb1[j] - mu) * s + pbe1[j];
    }
}

// ================= fused softmax-scatter + gemm1 + BN stats ================
__global__ void __launch_bounds__(512, 2)
k_sgemm1(const float* __restrict__ feat,
         const float* __restrict__ cw1, const float* __restrict__ cb1) {
    __shared__ float sft[16][CC];
    __shared__ float cfr[CC];
    __shared__ float pred[4][CC];
    int t = threadIdx.x, s = blockIdx.x;
    int wrp = t >> 5, lane = t & 31;

    {
        int row = g_members[s*16 + wrp];
        float4 v = *(const float4*)&feat[row*CC + lane*4];
        float m = fmaxf(fmaxf(v.x, v.y), fmaxf(v.z, v.w));
        for (int o = 16; o; o >>= 1) m = fmaxf(m, __shfl_xor_sync(~0u, m, o));
        float e0 = __expf(v.x - m), e1 = __expf(v.y - m);
        float e2 = __expf(v.z - m), e3 = __expf(v.w - m);
        float sum = e0 + e1 + e2 + e3;
        for (int o = 16; o; o >>= 1) sum += __shfl_xor_sync(~0u, sum, o);
        float inv = 1.f / sum;
        float4 r; r.x = e0*inv; r.y = e1*inv; r.z = e2*inv; r.w = e3*inv;
        *(float4*)&sft[wrp][lane*4] = r;
    }
    __syncthreads();
    if (t < CC) {
        float a = 0.f;
        #pragma unroll
        for (int r = 0; r < 16; r++) a += sft[r][t];
        cfr[t] = a;
    }
    __syncthreads();
    {
        int c = t & (CC-1), ks = t >> 7;
        float acc = 0.f;
        int k0 = ks * 32;
        #pragma unroll 8
        for (int k = k0; k < k0 + 32; k++)
            acc = fmaf(cfr[k], cw1[k*CC + c], acc);
        pred[ks][c] = acc;
    }
    __syncthreads();
    if (t < CC) {
        float v = pred[0][t] + pred[1][t] + pred[2][t] + pred[3][t] + cb1[t];
        g_hid[s*CC + t] = v;
        atomicAdd(&g_acc.s1[t], v);
        atomicAdd(&g_acc.s2[t], v*v);
    }
}

// ================= BN+ReLU + gemm2 + K,V projections (k-split) =============
__global__ void __launch_bounds__(512, 2)
k_gemm2kv(const float* __restrict__ cw2, const float* __restrict__ cb2,
          const float* __restrict__ cg1, const float* __restrict__ cbe1,
          const float* __restrict__ wk,  const float* __restrict__ bk,
          const float* __restrict__ wv,  const float* __restrict__ bv) {
    __shared__ float act[CC], hrow[CC];
    __shared__ float pr[4][CC];
    int t = threadIdx.x, r = blockIdx.x;

    if (t < CC) {
        float mu  = g_acc.s1[t] * (1.f/NSV);
        float var = g_acc.s2[t] * (1.f/NSV) - mu * mu;
        float A = cg1[t] * rsqrtf(var + EPSF);
        float D = cbe1[t] - mu * A;
        act[t] = fmaxf(fmaf(g_hid[r*CC + t], A, D), 0.f);
    }
    __syncthreads();
    {
        int c = t & (CC-1), ks = t >> 7;
        float acc = 0.f;
        int k0 = ks * 32;
        #pragma unroll 8
        for (int k = k0; k < k0 + 32; k++)
            acc = fmaf(act[k], cw2[k*CC + c], acc);
        pr[ks][c] = acc;
    }
    __syncthreads();
    if (t < CC) hrow[t] = pr[0][t] + pr[1][t] + pr[2][t] + pr[3][t] + cb2[t];
    __syncthreads();
    {
        int c = t & (CC-1), sel = t >> 7;
        const float* W = (sel < 2) ? wk : wv;
        int k0 = (sel & 1) * 64;
        float acc = 0.f;
        #pragma unroll 8
        for (int k = k0; k < k0 + 64; k++)
            acc = fmaf(hrow[k], W[k*CC + c], acc);
        pr[sel][c] = acc;
    }
    __syncthreads();
    if (t < 2*CC) {
        int c = t & (CC-1), proj = t >> 7;
        float val = pr[proj*2][c] + pr[proj*2+1][c] + (proj ? bv[c] : bk[c]);
        if (proj) g_v[r*CC + c]   = val;
        else      g_kT[c*NSV + r] = val;
    }
}

// ================= fully fused attention (fp16 satt, 3 blocks/SM) ==========
// smem float layout (offsets in floats):
//  sfeatT [k][g]   0      .. 1024
//  sqT    [c][g]   1024   .. 2048
//  satt_h [h][g][s]2048   .. 10240   (fp16; first 1024 floats reused grp1 partials)
//  spb    [g][s]   10240  .. 12288   (reused as sctxT [c][g] after phase 5)
//  st     [j][g]   12288  .. 12800
//  sw4    [j][4]   12800  .. 13056
//  spw2   [j]      13056  .. 13120
//  sred            13120  .. 13184
//  spos            13184  .. 13208
#define ATTN_FLOATS 13208
__global__ void __launch_bounds__(256, 3)
k_attn(const int* __restrict__ idx, const float* __restrict__ feat,
       const float* __restrict__ wq, const float* __restrict__ bq,
       const float* __restrict__ wo, const float* __restrict__ bo,
       const float* __restrict__ lng, const float* __restrict__ lnb,
       const float* __restrict__ pw2, const float* __restrict__ pb2) {
    extern __shared__ float sm[];
    float*  sfeatT = sm;
    float*  sqT    = sm + 1024;
    __half* satt_h = (__half*)(sm + 2048);
    float*  spart1 = sm + 2048;
    float*  spb    = sm + 10240;
    float*  sctxT  = sm + 10240;
    float*  st     = sm + 12288;
    float*  sw4    = sm + 12800;
    float*  spw2   = sm + 13056;
    float*  sred   = sm + 13120;
    float*  spos   = sm + 13184;

    int t = threadIdx.x;
    int n0 = blockIdx.x * GQ;
    int c = t & (CC-1), grp = t >> 7, g0 = grp * 4;

    // ---- phase 1: stage constants + features ----
    { int j = t >> 2, a = t & 3; sw4[t] = g_pweff[a*64 + j]; }
    if (t < 64) spw2[t] = pw2[t];
    if (t < GQ*3) spos[t] = (float)idx[(n0 + t/3)*4 + 1 + (t%3)];
    #pragma unroll
    for (int i = 0; i < 4; i++) {
        int li = t + 256*i;
        sfeatT[(li & (CC-1))*GQ + (li >> 7)] = feat[n0*CC + li];
    }
    __syncthreads();

    // ---- phase 2: t_j(g) table ----
    #pragma unroll
    for (int p = t; p < 64*GQ; p += 256) {
        int j = p >> 3, g = p & 7;
        float4 w = *(const float4*)&sw4[j*4];
        st[p] = fmaf(spos[g*3], w.x, fmaf(spos[g*3+1], w.y, fmaf(spos[g*3+2], w.z, w.w)));
    }
    __syncthreads();

    // ---- phases 3+4 MERGED: q-proj + pbias (independent stall profiles) ---
    {
        float b = bq[c];
        ull a01 = pk(b, b), a23 = pk(b, b);
        #pragma unroll 4
        for (int k = 0; k < CC; k++) {
            float w = wq[k*CC + c];
            ull wd = pk(w, w);
            ulonglong2 f = *(const ulonglong2*)&sfeatT[k*GQ + g0];
            FMA2(a01, f.x, wd, a01);
            FMA2(a23, f.y, wd, a23);
        }
        float q0,q1,q2,q3;
        upk(q0,q1,a01); upk(q2,q3,a23);
        float4 qo; qo.x = q0*0.25f; qo.y = q1*0.25f; qo.z = q2*0.25f; qo.w = q3*0.25f;
        *(float4*)&sqT[c*GQ + g0] = qo;

        int4 u = g_unq[t];
        float ux = (float)u.y, uy = (float)u.z, uz = (float)u.w;
        float pbv = pb2[0];
        float pb[8];
        #pragma unroll
        for (int g = 0; g < 8; g++) pb[g] = pbv;
        #pragma unroll 2
        for (int j = 0; j < 64; j++) {
            float4 w = *(const float4*)&sw4[j*4];
            float uj = fmaf(ux, w.x, fmaf(uy, w.y, uz * w.z));
            float w2j = spw2[j];
            float4 tA = *(const float4*)&st[j*8];
            float4 tB = *(const float4*)&st[j*8 + 4];
            pb[0] = fmaf(fmaxf(tA.x - uj, 0.f), w2j, pb[0]);
            pb[1] = fmaf(fmaxf(tA.y - uj, 0.f), w2j, pb[1]);
            pb[2] = fmaf(fmaxf(tA.z - uj, 0.f), w2j, pb[2]);
            pb[3] = fmaf(fmaxf(tA.w - uj, 0.f), w2j, pb[3]);
            pb[4] = fmaf(fmaxf(tB.x - uj, 0.f), w2j, pb[4]);
            pb[5] = fmaf(fmaxf(tB.y - uj, 0.f), w2j, pb[5]);
            pb[6] = fmaf(fmaxf(tB.z - uj, 0.f), w2j, pb[6]);
            pb[7] = fmaf(fmaxf(tB.w - uj, 0.f), w2j, pb[7]);
        }
        #pragma unroll
        for (int g = 0; g < 8; g++) spb[g*NSV + t] = pb[g];
    }
    __syncthreads();

    // ---- phase 5: scores + softmax (no max pass), two g-halves for regs ---
    // lane mapping s = ln*4 + {0,128}; satt stored as fp16; loads as ull pairs
    {
        int h = t >> 5, ln = t & 31;
        int sA = ln * 4, sB = sA + 128;
        #pragma unroll
        for (int gh = 0; gh < 2; gh++) {
            ull acc[4][4];
            #pragma unroll
            for (int g = 0; g < 4; g++) {
                ulonglong2 pA = *(const ulonglong2*)&spb[(gh*4 + g)*NSV + sA];
                ulonglong2 pB = *(const ulonglong2*)&spb[(gh*4 + g)*NSV + sB];
                acc[g][0] = pA.x; acc[g][1] = pA.y;
                acc[g][2] = pB.x; acc[g][3] = pB.y;
            }
            #pragma unroll 4
            for (int c16 = 0; c16 < DHD; c16++) {
                int cix = h*DHD + c16;
                float4 qA = *(const float4*)&sqT[cix*GQ + gh*4];
                ulonglong2 kA = *(const ulonglong2*)&g_kT[cix*NSV + sA];
                ulonglong2 kB = *(const ulonglong2*)&g_kT[cix*NSV + sB];
                float qs[4] = {qA.x, qA.y, qA.z, qA.w};
                #pragma unroll
                for (int g = 0; g < 4; g++) {
                    ull qd = pk(qs[g], qs[g]);
                    FMA2(acc[g][0], kA.x, qd, acc[g][0]);
                    FMA2(acc[g][1], kA.y, qd, acc[g][1]);
                    FMA2(acc[g][2], kB.x, qd, acc[g][2]);
                    FMA2(acc[g][3], kB.y, qd, acc[g][3]);
                }
            }
            #pragma unroll
            for (int g = 0; g < 4; g++) {
                float x0,x1,x2,x3,x4,x5,x6,x7;
                upk(x0,x1,acc[g][0]); upk(x2,x3,acc[g][1]);
                upk(x4,x5,acc[g][2]); upk(x6,x7,acc[g][3]);
                x0 = __expf(x0); x1 = __expf(x1);
                x2 = __expf(x2); x3 = __expf(x3);
                x4 = __expf(x4); x5 = __expf(x5);
                x6 = __expf(x6); x7 = __expf(x7);
                float sum = ((x0+x1)+(x2+x3)) + ((x4+x5)+(x6+x7));
                for (int o = 16; o; o >>= 1) sum += __shfl_xor_sync(~0u, sum, o);
                float inv = 1.f / sum;
                __half* row = &satt_h[(h*8 + gh*4 + g)*NSV];
                *(__half2*)&row[sA]     = __floats2half2_rn(x0*inv, x1*inv);
                *(__half2*)&row[sA + 2] = __floats2half2_rn(x2*inv, x3*inv);
                *(__half2*)&row[sB]     = __floats2half2_rn(x4*inv, x5*inv);
                *(__half2*)&row[sB + 2] = __floats2half2_rn(x6*inv, x7*inv);
            }
        }
    }
    __syncthreads();

    // ---- phase 7: attn @ V — s-range split across grps, fp16 a rows ------
    {
        int hh = c >> 4;
        int sbase = grp * 128;
        const __half* abase = &satt_h[hh*8*NSV + sbase];
        ull A[8];
        #pragma unroll
        for (int g = 0; g < 8; g++) A[g] = 0ull;
        #pragma unroll 4
        for (int s4 = 0; s4 < 32; s4++) {
            int s = s4 * 4;
            const float* vb = &g_v[(sbase + s)*CC + c];
            float v0 = vb[0], v1 = vb[CC], v2 = vb[2*CC], v3 = vb[3*CC];
            ull vlo = pk(v0, v1), vhi = pk(v2, v3);
            #pragma unroll
            for (int g = 0; g < 8; g++) {
                __half2 h01 = *(const __half2*)&abase[g*NSV + s];
                __half2 h23 = *(const __half2*)&abase[g*NSV + s + 2];
                float2 f01 = __half22float2(h01);
                float2 f23 = __half22float2(h23);
                FMA2(A[g], pk2(f01), vlo, A[g]);
                FMA2(A[g], pk2(f23), vhi, A[g]);
            }
        }
        float part[8];
        #pragma unroll
        for (int g = 0; g < 8; g++) {
            float p0, p1;
            upk(p0, p1, A[g]);
            part[g] = p0 + p1;
        }
        __syncthreads();
        float* dst = grp ? &spart1[c*8] : &sctxT[c*8];
        *(float4*)dst       = *(const float4*)&part[0];
        *(float4*)(dst + 4) = *(const float4*)&part[4];
    }
    __syncthreads();
    // combine halves into sctxT[c][g]
    {
        int cc = t & (CC-1), gh = t >> 7;
        float4 h0 = *(const float4*)&sctxT[cc*8 + gh*4];
        float4 h1 = *(const float4*)&spart1[cc*8 + gh*4];
        float4 cx; cx.x = h0.x + h1.x; cx.y = h0.y + h1.y;
        cx.z = h0.z + h1.z; cx.w = h0.w + h1.w;
        *(float4*)&sctxT[cc*8 + gh*4] = cx;
    }
    __syncthreads();

    // ---- phase 8: o-proj + residual + LayerNorm ----
    {
        float b = bo[c];
        ull a01 = pk(b, b), a23 = pk(b, b);
        #pragma unroll 4
        for (int k = 0; k < CC; k++) {
            float w = wo[k*CC + c];
            ull wd = pk(w, w);
            ulonglong2 cx = *(const ulonglong2*)&sctxT[k*GQ + g0];
            FMA2(a01, cx.x, wd, a01);
            FMA2(a23, cx.y, wd, a23);
        }
        float o0,o1,o2,o3;
        upk(o0,o1,a01); upk(o2,o3,a23);
        float yv[4];
        float4 fr = *(const float4*)&sfeatT[c*GQ + g0];
        yv[0] = fr.x + o0; yv[1] = fr.y + o1; yv[2] = fr.z + o2; yv[3] = fr.w + o3;

        int warp = t >> 5, lane = t & 31, w4 = warp & 3;
        #pragma unroll
        for (int gg = 0; gg < 4; gg++) {
            float s = yv[gg], ss = yv[gg]*yv[gg];
            for (int o = 16; o; o >>= 1) {
                s  += __shfl_xor_sync(~0u, s, o);
                ss += __shfl_xor_sync(~0u, ss, o);
            }
            if (lane == 0) {
                sred[(g0+gg)*4 + w4]      = s;
                sred[32 + (g0+gg)*4 + w4] = ss;
            }
        }
        __syncthreads();
        float lg = lng[c], lb = lnb[c];
        #pragma unroll
        for (int gg = 0; gg < 4; gg++) {
            int g = g0 + gg;
            float s  = sred[g*4+0] + sred[g*4+1] + sred[g*4+2] + sred[g*4+3];
            float ss = sred[32+g*4+0] + sred[32+g*4+1] + sred[32+g*4+2] + sred[32+g*4+3];
            float mu = s * (1.f/CC), var = ss * (1.f/CC) - mu*mu;
            g_y[(n0+g)*CC + c] = (yv[gg] - mu) * rsqrtf(var + EPSF) * lg + lb;
        }
    }
}

// ================= submanifold 3^3 conv (float4 y, reg-prefetch W) =========
__global__ void __launch_bounds__(160, 4)
k_conv(const int* __restrict__ idx, const float* __restrict__ segw,
       const float* __restrict__ segb, float* __restrict__ out) {
    __shared__ float sW[CC*NCL];
    __shared__ int4 svox[16];
    int t = threadIdx.x;
    int n0 = blockIdx.x * 16;
    if (t < 16) svox[t] = ((const int4*)idx)[n0 + t];

    float4 wr0, wr1, wr2, wr3;
    {
        const float4* src = (const float4*)segw;
        wr0 = src[t]; wr1 = src[t + 160]; wr2 = src[t + 320]; wr3 = src[t + 480];
    }
    __syncthreads();

    int v = t / 10, op = t - v * 10;
    int4 pv = svox[v];
    float2 bb = *(const float2*)&segb[op*2];
    ull acc0 = pk(bb.x, bb.y), acc1 = 0ull;

    for (int d = 0; d < 27; d++) {
        float4* dst = (float4*)sW;
        dst[t] = wr0; dst[t + 160] = wr1; dst[t + 320] = wr2; dst[t + 480] = wr3;
        if (d < 26) {
            const float4* src = (const float4*)&segw[(d+1)*CC*NCL];
            wr0 = src[t]; wr1 = src[t + 160]; wr2 = src[t + 320]; wr3 = src[t + 480];
        }
        __syncthreads();

        int ax = d / 9, ay = (d / 3) % 3, az = d % 3;
        int x = pv.y + ax - 1, y = pv.z + ay - 1, z = pv.w + az - 1;
        if (x >= 0 && x < GXD && y >= 0 && y < GYD && z >= 0 && z < GZD) {
            int m = g_map[((pv.x * GXD + x) * GYD + y) * GZD + z];
            if (m > 0) {
                const float4* yr4 = (const float4*)&g_y[(m-1)*CC];
                const float* wrow = &sW[op*2];
                #pragma unroll 4
                for (int c4 = 0; c4 < CC/4; c4++) {
                    float4 yv = yr4[c4];
                    int cb = c4 * 4 * NCL;
                    FMA2(acc0, pk(yv.x, yv.x), *(const ull*)&wrow[cb],         acc0);
                    FMA2(acc1, pk(yv.y, yv.y), *(const ull*)&wrow[cb + NCL],   acc1);
                    FMA2(acc0, pk(yv.z, yv.z), *(const ull*)&wrow[cb + 2*NCL], acc0);
                    FMA2(acc1, pk(yv.w, yv.w), *(const ull*)&wrow[cb + 3*NCL], acc1);
                }
            }
        }
        __syncthreads();
    }
    float a0, a1, b0, b1;
    upk(a0, a1, acc0); upk(b0, b1, acc1);
    float2 res; res.x = a0 + b0; res.y = a1 + b1;
    *(float2*)&out[(n0 + v)*NCL + op*2] = res;
}

// --------------------------------------------------------------------------
extern "C" void kernel_launch(void* const* d_in, const int* in_sizes, int n_in,
                              void* d_out, int out_size) {
    const int*   idx  = (const int*)  d_in[0];
    const float* feat = (const float*)d_in[1];
    const float* cw1  = (const float*)d_in[2];
    const float* cb1  = (const float*)d_in[3];
    const float* cg1  = (const float*)d_in[4];
    const float* cbe1 = (const float*)d_in[5];
    const float* cw2  = (const float*)d_in[6];
    const float* cb2  = (const float*)d_in[7];
    const float* pw1  = (const float*)d_in[8];
    const float* pb1  = (const float*)d_in[9];
    const float* pg1  = (const float*)d_in[10];
    const float* pbe1 = (const float*)d_in[11];
    const float* pw2  = (const float*)d_in[12];
    const float* pb2  = (const float*)d_in[13];
    const float* wq   = (const float*)d_in[14];
    const float* bq   = (const float*)d_in[15];
    const float* wk   = (const float*)d_in[16];
    const float* bk   = (const float*)d_in[17];
    const float* wv   = (const float*)d_in[18];
    const float* bv   = (const float*)d_in[19];
    const float* wo   = (const float*)d_in[20];
    const float* bo   = (const float*)d_in[21];
    const float* ln_g = (const float*)d_in[22];
    const float* ln_b = (const float*)d_in[23];
    const float* segw = (const float*)d_in[24];
    const float* segb = (const float*)d_in[25];

    constexpr int ATTN_SMEM = ATTN_FLOATS * 4;
    cudaFuncSetAttribute(k_attn, cudaFuncAttributeMaxDynamicSharedMemorySize, ATTN_SMEM);

    k_prep    <<<1, 256>>>(idx, pw1, pb1, pg1, pbe1);
    k_sgemm1  <<<NSV, 512>>>(feat, cw1, cb1);
    k_gemm2kv <<<NSV, 512>>>(cw2, cb2, cg1, cbe1, wk, bk, wv, bv);
    k_attn    <<<NV/GQ, 256, ATTN_SMEM>>>(idx, feat, wq, bq, wo, bo, ln_g, ln_b, pw2, pb2);
    k_conv    <<<NV/16, 160>>>(idx, segw, segb, (float*)d_out);
}